// round 7
// baseline (speedup 1.0000x reference)
#include <cuda_runtime.h>
#include <cstdint>

#define B_    16384
#define CURD  2048
#define FEAT_ 2048
#define HEADS_ 16
#define HDIM  128

#define NTHREADS 256
#define BM 128
#define BN 128
#define BK 32
#define LDSR 36                       // 32 + 4 pad floats per row
#define TILE_F (BM*LDSR)              // floats per buffer per matrix
#define SMEM_BYTES (4*TILE_F*4)       // A(2 bufs) + B(2 bufs) = 73728 B

// ---------------- scratch (device globals; no allocation allowed) ----------
__device__ float g_q  [(size_t)B_*FEAT_];
__device__ float g_kv2[(size_t)B_*2*FEAT_];
__device__ float g_kv3[(size_t)B_*2*FEAT_];
__device__ float g_att[(size_t)B_*FEAT_];
__device__ float g_y  [(size_t)B_*CURD];

// ---------------- helpers ----------------
__device__ __forceinline__ float to_tf32(float x) {
    uint32_t r;
    asm("cvt.rna.tf32.f32 %0, %1;" : "=r"(r) : "f"(x));
    return __uint_as_float(r);
}

// fp32 -> tf32 bits (round-to-nearest; kills truncation bias)
__device__ __forceinline__ uint32_t tf32b(float x) {
    uint32_t r;
    asm("cvt.rna.tf32.f32 %0, %1;" : "=r"(r) : "f"(x));
    return r;
}

__device__ __forceinline__ void cp16(float* s, const float* g) {
    uint32_t sa = (uint32_t)__cvta_generic_to_shared(s);
    asm volatile("cp.async.cg.shared.global [%0], [%1], 16;\n" :: "r"(sa), "l"(g));
}

__device__ __forceinline__ void mma_tf32(float* c, const uint32_t* a, const uint32_t* b) {
    asm volatile(
        "mma.sync.aligned.m16n8k8.row.col.f32.tf32.tf32.f32 "
        "{%0,%1,%2,%3}, {%4,%5,%6,%7}, {%8,%9}, {%0,%1,%2,%3};"
        : "+f"(c[0]), "+f"(c[1]), "+f"(c[2]), "+f"(c[3])
        : "r"(a[0]), "r"(a[1]), "r"(a[2]), "r"(a[3]),
          "r"(b[0]), "r"(b[1]));
}

// ---------------- TF32 GEMM:  C[M,N] = A[M,K] @ W[N,K]^T + bias (+res)
// A and W are raw fp32; fragments are RNA-rounded to tf32 right before MMA.
// W can be split into two stacked halves (W0 rows [0,Nsplit), W1 the rest),
// so k- and v-projections sharing the same A run as one N=4096 launch.
template<bool RES>
__global__ __launch_bounds__(NTHREADS, 2)
void gemm_tf32_kernel(const float* __restrict__ A,
                      const float* __restrict__ W0,
                      const float* __restrict__ W1,
                      int Nsplit,
                      const float* __restrict__ bias0,
                      const float* __restrict__ bias1,
                      const float* __restrict__ res,
                      float* __restrict__ C,
                      int N, int K) {
    extern __shared__ float smem[];
    float* As = smem;
    float* Bs = smem + 2*TILE_F;

    const int nb = blockIdx.x, mb = blockIdx.y;
    const float* Wp; const float* biasP; int nloc0;
    if (nb*BN < Nsplit) { Wp = W0; biasP = bias0; nloc0 = nb*BN; }
    else                { Wp = W1; biasP = bias1; nloc0 = nb*BN - Nsplit; }

    const int tid  = threadIdx.x;
    const int lrow = tid >> 3;            // 0..31
    const int lc4  = (tid & 7) << 2;      // 0,4,...,28 (floats)
    const float* Ag = A  + (size_t)(mb*BM + lrow)*K + lc4;
    const float* Bg = Wp + (size_t)(nloc0 + lrow)*K + lc4;

    const int warp = tid >> 5, lane = tid & 31;
    const int wm = warp & 3, wn = warp >> 2;     // warp tile 32(M) x 64(N)
    const int qr = lane >> 2, qc = lane & 3;

    float acc[2][8][4];
    #pragma unroll
    for (int i = 0; i < 2; i++)
        #pragma unroll
        for (int j = 0; j < 8; j++)
            #pragma unroll
            for (int l = 0; l < 4; l++) acc[i][j][l] = 0.f;

    const int KT = K / BK;

    // prologue: stage tile 0
    {
        float* Asd = As + lrow*LDSR + lc4;
        float* Bsd = Bs + lrow*LDSR + lc4;
        #pragma unroll
        for (int i = 0; i < 4; i++) {
            cp16(Asd + i*32*LDSR, Ag + (size_t)i*32*K);
            cp16(Bsd + i*32*LDSR, Bg + (size_t)i*32*K);
        }
        asm volatile("cp.async.commit_group;\n" ::);
        asm volatile("cp.async.wait_group 0;\n" ::);
        __syncthreads();
    }

    int buf = 0;
    for (int kt = 0; kt < KT; kt++) {
        if (kt + 1 < KT) {
            int nbuf = buf ^ 1;
            float* Asd = As + nbuf*TILE_F + lrow*LDSR + lc4;
            float* Bsd = Bs + nbuf*TILE_F + lrow*LDSR + lc4;
            const float* Agk = Ag + (kt+1)*BK;
            const float* Bgk = Bg + (kt+1)*BK;
            #pragma unroll
            for (int i = 0; i < 4; i++) {
                cp16(Asd + i*32*LDSR, Agk + (size_t)i*32*K);
                cp16(Bsd + i*32*LDSR, Bgk + (size_t)i*32*K);
            }
            asm volatile("cp.async.commit_group;\n" ::);
        }

        const float* As_ = As + buf*TILE_F;
        const float* Bs_ = Bs + buf*TILE_F;
        #pragma unroll
        for (int ks = 0; ks < BK/8; ks++) {
            const int k = ks*8;
            uint32_t afr[2][4];
            #pragma unroll
            for (int mt = 0; mt < 2; mt++) {
                const float* p = As_ + (wm*32 + mt*16 + qr)*LDSR + k + qc;
                afr[mt][0] = tf32b(p[0]);
                afr[mt][1] = tf32b(p[8*LDSR]);
                afr[mt][2] = tf32b(p[4]);
                afr[mt][3] = tf32b(p[8*LDSR + 4]);
            }
            uint32_t bfr[8][2];
            #pragma unroll
            for (int nt = 0; nt < 8; nt++) {
                const float* p = Bs_ + (wn*64 + nt*8 + qr)*LDSR + k + qc;
                bfr[nt][0] = tf32b(p[0]);
                bfr[nt][1] = tf32b(p[4]);
            }
            #pragma unroll
            for (int mt = 0; mt < 2; mt++)
                #pragma unroll
                for (int nt = 0; nt < 8; nt++)
                    mma_tf32(acc[mt][nt], afr[mt], bfr[nt]);
        }

        asm volatile("cp.async.wait_group 0;\n" ::);
        __syncthreads();
        buf ^= 1;
    }

    // epilogue: bias (+residual), fp32 stores
    float bv0[8], bv1[8];
    #pragma unroll
    for (int nt = 0; nt < 8; nt++) {
        int cl = nloc0 + wn*64 + nt*8 + qc*2;
        bv0[nt] = biasP[cl];
        bv1[nt] = biasP[cl + 1];
    }
    #pragma unroll
    for (int mt = 0; mt < 2; mt++) {
        int r0 = mb*BM + wm*32 + mt*16 + qr;
        #pragma unroll
        for (int nt = 0; nt < 8; nt++) {
            int c0 = nb*BN + wn*64 + nt*8 + qc*2;
            size_t o0 = (size_t)r0*N + c0;
            size_t o1 = o0 + (size_t)8*N;
            float v0 = acc[mt][nt][0] + bv0[nt];
            float v1 = acc[mt][nt][1] + bv1[nt];
            float v2 = acc[mt][nt][2] + bv0[nt];
            float v3 = acc[mt][nt][3] + bv1[nt];
            if (RES) {
                v0 += res[o0]; v1 += res[o0 + 1];
                v2 += res[o1]; v3 += res[o1 + 1];
            }
            *(float2*)(C + o0) = make_float2(v0, v1);
            *(float2*)(C + o1) = make_float2(v2, v3);
        }
    }
}

// ---------------- attention: one warp per (b, h); 2-key softmax -----------
__global__ void attn_kernel(const float* __restrict__ q,
                            const float* __restrict__ kv2,
                            const float* __restrict__ kv3,
                            float* __restrict__ attn,
                            float* __restrict__ wout) {
    int gw   = (blockIdx.x * blockDim.x + threadIdx.x) >> 5;   // b*16 + h
    int lane = threadIdx.x & 31;
    int b = gw >> 4;
    int h = gw & 15;
    size_t qoff = (size_t)b*FEAT_     + h*HDIM + lane*4;
    size_t koff = (size_t)b*(2*FEAT_) + h*HDIM + lane*4;

    float4 qv = *(const float4*)(q   + qoff);
    float4 k2 = *(const float4*)(kv2 + koff);
    float4 k3 = *(const float4*)(kv3 + koff);
    float4 v2 = *(const float4*)(kv2 + koff + FEAT_);
    float4 v3 = *(const float4*)(kv3 + koff + FEAT_);

    float s2 = qv.x*k2.x + qv.y*k2.y + qv.z*k2.z + qv.w*k2.w;
    float s3 = qv.x*k3.x + qv.y*k3.y + qv.z*k3.z + qv.w*k3.w;
    #pragma unroll
    for (int o = 16; o; o >>= 1) {
        s2 += __shfl_xor_sync(0xffffffffu, s2, o);
        s3 += __shfl_xor_sync(0xffffffffu, s3, o);
    }
    const float scale = 0.08838834764831845f;   // 1/sqrt(128)
    s2 *= scale; s3 *= scale;
    float m  = fmaxf(s2, s3);
    float e2 = expf(s2 - m), e3 = expf(s3 - m);
    float inv = 1.f / (e2 + e3);
    float w2 = e2 * inv, w3 = e3 * inv;

    float4 o4;   // pre-round to tf32 (free accuracy for the Wo GEMM)
    o4.x = to_tf32(w2*v2.x + w3*v3.x);
    o4.y = to_tf32(w2*v2.y + w3*v3.y);
    o4.z = to_tf32(w2*v2.z + w3*v3.z);
    o4.w = to_tf32(w2*v2.w + w3*v3.w);
    *(float4*)(attn + qoff) = o4;

    if (lane == 0) {
        wout[(size_t)gw*2]     = w2;
        wout[(size_t)gw*2 + 1] = w3;
    }
}

// ---------------- LayerNorm: one block per row ----------------------------
__global__ void ln_kernel(const float* __restrict__ y,
                          const float* __restrict__ lw,
                          const float* __restrict__ lb,
                          float* __restrict__ out) {
    __shared__ float shs[8], shq[8];
    int row = blockIdx.x, t = threadIdx.x;
    const float4* yr = (const float4*)(y + (size_t)row*CURD);
    float4 a = yr[t];
    float4 b = yr[256 + t];
    float s  = a.x+a.y+a.z+a.w + b.x+b.y+b.z+b.w;
    float qq = a.x*a.x+a.y*a.y+a.z*a.z+a.w*a.w
             + b.x*b.x+b.y*b.y+b.z*b.z+b.w*b.w;
    #pragma unroll
    for (int o = 16; o; o >>= 1) {
        s  += __shfl_xor_sync(0xffffffffu, s,  o);
        qq += __shfl_xor_sync(0xffffffffu, qq, o);
    }
    int warp = t >> 5;
    if ((t & 31) == 0) { shs[warp] = s; shq[warp] = qq; }
    __syncthreads();
    float S = 0.f, Q = 0.f;
    #pragma unroll
    for (int i = 0; i < 8; i++) { S += shs[i]; Q += shq[i]; }
    float mean = S * (1.f/2048.f);
    float inv  = rsqrtf(Q * (1.f/2048.f) - mean*mean + 1e-5f);

    const float4* lw4 = (const float4*)lw;
    const float4* lb4 = (const float4*)lb;
    float4* orow = (float4*)(out + (size_t)row*CURD);
    float4 w, z, o4;
    w = lw4[t];       z = lb4[t];
    o4.x = w.x*(a.x-mean)*inv + z.x;
    o4.y = w.y*(a.y-mean)*inv + z.y;
    o4.z = w.z*(a.z-mean)*inv + z.z;
    o4.w = w.w*(a.w-mean)*inv + z.w;
    orow[t] = o4;
    w = lw4[256+t];   z = lb4[256+t];
    o4.x = w.x*(b.x-mean)*inv + z.x;
    o4.y = w.y*(b.y-mean)*inv + z.y;
    o4.z = w.z*(b.z-mean)*inv + z.z;
    o4.w = w.w*(b.w-mean)*inv + z.w;
    orow[256+t] = o4;
}

// ---------------- launch ---------------------------------------------------
extern "C" void kernel_launch(void* const* d_in, const int* in_sizes, int n_in,
                              void* d_out, int out_size) {
    const float* x   = (const float*)d_in[0];
    const float* v2  = (const float*)d_in[1];
    const float* v3  = (const float*)d_in[2];
    const float* Wq  = (const float*)d_in[3];
    const float* bq  = (const float*)d_in[4];
    const float* Wk2 = (const float*)d_in[5];
    const float* bk2 = (const float*)d_in[6];
    const float* Wk3 = (const float*)d_in[7];
    const float* bk3 = (const float*)d_in[8];
    const float* Wv2 = (const float*)d_in[9];
    const float* bv2 = (const float*)d_in[10];
    const float* Wv3 = (const float*)d_in[11];
    const float* bv3 = (const float*)d_in[12];
    const float* Wo  = (const float*)d_in[13];
    const float* bo  = (const float*)d_in[14];
    const float* lw  = (const float*)d_in[15];
    const float* lb  = (const float*)d_in[16];
    float* out = (float*)d_out;

    float *qb, *kv2, *kv3, *attn, *yb;
    cudaGetSymbolAddress((void**)&qb,   g_q);
    cudaGetSymbolAddress((void**)&kv2,  g_kv2);
    cudaGetSymbolAddress((void**)&kv3,  g_kv3);
    cudaGetSymbolAddress((void**)&attn, g_att);
    cudaGetSymbolAddress((void**)&yb,   g_y);

    cudaFuncSetAttribute((const void*)gemm_tf32_kernel<false>,
                         cudaFuncAttributeMaxDynamicSharedMemorySize, SMEM_BYTES);
    cudaFuncSetAttribute((const void*)gemm_tf32_kernel<true>,
                         cudaFuncAttributeMaxDynamicSharedMemorySize, SMEM_BYTES);

    dim3 blk(NTHREADS);
    // q = x @ Wq^T + bq
    gemm_tf32_kernel<false><<<dim3(FEAT_/BN, B_/BM), blk, SMEM_BYTES>>>(
        x, Wq, Wq, FEAT_, bq, bq, nullptr, qb, FEAT_, CURD);
    // [k2 | v2] = v2 @ [Wk2; Wv2]^T + [bk2; bv2]
    gemm_tf32_kernel<false><<<dim3(2*FEAT_/BN, B_/BM), blk, SMEM_BYTES>>>(
        v2, Wk2, Wv2, FEAT_, bk2, bv2, nullptr, kv2, 2*FEAT_, FEAT_);
    // [k3 | v3] = v3 @ [Wk3; Wv3]^T + [bk3; bv3]
    gemm_tf32_kernel<false><<<dim3(2*FEAT_/BN, B_/BM), blk, SMEM_BYTES>>>(
        v3, Wk3, Wv3, FEAT_, bk3, bv3, nullptr, kv3, 2*FEAT_, FEAT_);

    // attention + attn_weights (written to the tail of d_out)
    size_t woff = (size_t)out_size - (size_t)B_*HEADS_*2;
    attn_kernel<<<B_*HEADS_/8, 256>>>(qb, kv2, kv3, attn, out + woff);

    // y = x + attn @ Wo^T + bo   (residual fused, exact fp32 x)
    gemm_tf32_kernel<true><<<dim3(CURD/BN, B_/BM), blk, SMEM_BYTES>>>(
        attn, Wo, Wo, CURD, bo, bo, x, yb, CURD, FEAT_);

    // LayerNorm -> d_out
    ln_kernel<<<B_, 256>>>(yb, lw, lb, out);
}

// round 8
// speedup vs baseline: 1.5288x; 1.5288x over previous
#include <cuda_runtime.h>
#include <cuda_fp16.h>
#include <cstdint>

#define B_    16384
#define CURD  2048
#define FEAT_ 2048
#define HEADS_ 16
#define HDIM  128

#define NTHREADS 256
#define BM 128
#define BN 128
#define BK 32
#define LDSRH 40                       // 32 + 8 pad halves per row (conflict-free frag LDS)
#define TILE_H (BM*LDSRH)              // halves per buffer per matrix (5120)
#define SMEM_BYTES (4*TILE_H*2)        // A(2 bufs) + B(2 bufs) = 40960 B

// ---------------- scratch (device globals; no allocation allowed) ----------
__device__ __align__(16) __half g_xh [(size_t)B_*CURD];
__device__ __align__(16) __half g_v2h[(size_t)B_*FEAT_];
__device__ __align__(16) __half g_v3h[(size_t)B_*FEAT_];
__device__ __align__(16) __half g_wqh [(size_t)FEAT_*CURD];
__device__ __align__(16) __half g_wk2h[(size_t)FEAT_*FEAT_];
__device__ __align__(16) __half g_wv2h[(size_t)FEAT_*FEAT_];
__device__ __align__(16) __half g_wk3h[(size_t)FEAT_*FEAT_];
__device__ __align__(16) __half g_wv3h[(size_t)FEAT_*FEAT_];
__device__ __align__(16) __half g_woh [(size_t)CURD*FEAT_];
__device__ __align__(16) __half g_q  [(size_t)B_*FEAT_];
__device__ __align__(16) __half g_kv2[(size_t)B_*2*FEAT_];
__device__ __align__(16) __half g_kv3[(size_t)B_*2*FEAT_];
__device__ __align__(16) __half g_att[(size_t)B_*FEAT_];
__device__ __align__(16) float  g_y  [(size_t)B_*CURD];

// ---------------- helpers ----------------
__device__ __forceinline__ void cp16(__half* s, const __half* g) {
    uint32_t sa = (uint32_t)__cvta_generic_to_shared(s);
    asm volatile("cp.async.cg.shared.global [%0], [%1], 16;\n" :: "r"(sa), "l"(g));
}

__device__ __forceinline__ void mma_f16(float* c, const uint32_t* a, const uint32_t* b) {
    asm volatile(
        "mma.sync.aligned.m16n8k16.row.col.f32.f16.f16.f32 "
        "{%0,%1,%2,%3}, {%4,%5,%6,%7}, {%8,%9}, {%0,%1,%2,%3};"
        : "+f"(c[0]), "+f"(c[1]), "+f"(c[2]), "+f"(c[3])
        : "r"(a[0]), "r"(a[1]), "r"(a[2]), "r"(a[3]),
          "r"(b[0]), "r"(b[1]));
}

// ---------------- fp32 -> fp16 conversion (RN) ------------------------------
__global__ void conv_h_kernel(const float* __restrict__ in,
                              __half* __restrict__ out, long long n4) {
    long long i  = blockIdx.x * (long long)blockDim.x + threadIdx.x;
    long long st = (long long)gridDim.x * blockDim.x;
    const float4* in4 = (const float4*)in;
    __half2* o2 = (__half2*)out;
    for (; i < n4; i += st) {
        float4 v = in4[i];
        o2[2*i]   = __floats2half2_rn(v.x, v.y);
        o2[2*i+1] = __floats2half2_rn(v.z, v.w);
    }
}

// ---------------- FP16 GEMM:  C[M,N] = A[M,K] @ W[N,K]^T + bias (+res)
// W split into two stacked halves (W0 rows [0,Nsplit), W1 the rest) so fused
// k/v projections sharing the same A run as one N=4096 launch.
// HOUT: store C as fp16 (q/kv path). !HOUT: fp32 out with optional residual.
template<bool RES, bool HOUT>
__global__ __launch_bounds__(NTHREADS, 2)
void gemm_f16_kernel(const __half* __restrict__ A,
                     const __half* __restrict__ W0,
                     const __half* __restrict__ W1,
                     int Nsplit,
                     const float* __restrict__ bias0,
                     const float* __restrict__ bias1,
                     const float* __restrict__ res,
                     void* __restrict__ Cv,
                     int N, int K) {
    extern __shared__ __half smh[];
    __half* As = smh;
    __half* Bs = smh + 2*TILE_H;

    const int nb = blockIdx.x, mb = blockIdx.y;
    const __half* Wp; const float* biasP; int nloc0;
    if (nb*BN < Nsplit) { Wp = W0; biasP = bias0; nloc0 = nb*BN; }
    else                { Wp = W1; biasP = bias1; nloc0 = nb*BN - Nsplit; }

    const int tid  = threadIdx.x;
    const int lrow = tid >> 1;            // 0..127
    const int lch  = (tid & 1) << 4;      // 0 or 16 halves
    const __half* Ag = A  + (size_t)(mb*BM + lrow)*K + lch;
    const __half* Bg = Wp + (size_t)(nloc0 + lrow)*K + lch;

    const int warp = tid >> 5, lane = tid & 31;
    const int wm = warp & 3, wn = warp >> 2;     // warp tile 32(M) x 64(N)
    const int qr = lane >> 2, qc = lane & 3;

    float acc[2][8][4];
    #pragma unroll
    for (int i = 0; i < 2; i++)
        #pragma unroll
        for (int j = 0; j < 8; j++)
            #pragma unroll
            for (int l = 0; l < 4; l++) acc[i][j][l] = 0.f;

    const int KT = K / BK;

    // prologue: stage tile 0
    {
        __half* Asd = As + lrow*LDSRH + lch;
        __half* Bsd = Bs + lrow*LDSRH + lch;
        cp16(Asd,     Ag);
        cp16(Asd + 8, Ag + 8);
        cp16(Bsd,     Bg);
        cp16(Bsd + 8, Bg + 8);
        asm volatile("cp.async.commit_group;\n" ::);
        asm volatile("cp.async.wait_group 0;\n" ::);
        __syncthreads();
    }

    int buf = 0;
    for (int kt = 0; kt < KT; kt++) {
        if (kt + 1 < KT) {
            int nbuf = buf ^ 1;
            __half* Asd = As + nbuf*TILE_H + lrow*LDSRH + lch;
            __half* Bsd = Bs + nbuf*TILE_H + lrow*LDSRH + lch;
            const __half* Agk = Ag + (kt+1)*BK;
            const __half* Bgk = Bg + (kt+1)*BK;
            cp16(Asd,     Agk);
            cp16(Asd + 8, Agk + 8);
            cp16(Bsd,     Bgk);
            cp16(Bsd + 8, Bgk + 8);
            asm volatile("cp.async.commit_group;\n" ::);
        }

        const __half* As_ = As + buf*TILE_H;
        const __half* Bs_ = Bs + buf*TILE_H;
        #pragma unroll
        for (int ks = 0; ks < BK/16; ks++) {
            const int k = ks*16 + qc*2;
            uint32_t afr[2][4];
            #pragma unroll
            for (int mt = 0; mt < 2; mt++) {
                const __half* p = As_ + (wm*32 + mt*16 + qr)*LDSRH + k;
                afr[mt][0] = *(const uint32_t*)(p);
                afr[mt][1] = *(const uint32_t*)(p + 8*LDSRH);
                afr[mt][2] = *(const uint32_t*)(p + 8);
                afr[mt][3] = *(const uint32_t*)(p + 8*LDSRH + 8);
            }
            uint32_t bfr[8][2];
            #pragma unroll
            for (int nt = 0; nt < 8; nt++) {
                const __half* p = Bs_ + (wn*64 + nt*8 + qr)*LDSRH + k;
                bfr[nt][0] = *(const uint32_t*)(p);
                bfr[nt][1] = *(const uint32_t*)(p + 8);
            }
            #pragma unroll
            for (int mt = 0; mt < 2; mt++)
                #pragma unroll
                for (int nt = 0; nt < 8; nt++)
                    mma_f16(acc[mt][nt], afr[mt], bfr[nt]);
        }

        asm volatile("cp.async.wait_group 0;\n" ::);
        __syncthreads();
        buf ^= 1;
    }

    // epilogue: bias (+residual), fp16 or fp32 stores
    float bv0[8], bv1[8];
    #pragma unroll
    for (int nt = 0; nt < 8; nt++) {
        int cl = nloc0 + wn*64 + nt*8 + qc*2;
        bv0[nt] = biasP[cl];
        bv1[nt] = biasP[cl + 1];
    }
    #pragma unroll
    for (int mt = 0; mt < 2; mt++) {
        int r0 = mb*BM + wm*32 + mt*16 + qr;
        #pragma unroll
        for (int nt = 0; nt < 8; nt++) {
            int c0 = nb*BN + wn*64 + nt*8 + qc*2;
            size_t o0 = (size_t)r0*N + c0;
            size_t o1 = o0 + (size_t)8*N;
            float v0 = acc[mt][nt][0] + bv0[nt];
            float v1 = acc[mt][nt][1] + bv1[nt];
            float v2 = acc[mt][nt][2] + bv0[nt];
            float v3 = acc[mt][nt][3] + bv1[nt];
            if (HOUT) {
                __half* C = (__half*)Cv;
                *(__half2*)(C + o0) = __floats2half2_rn(v0, v1);
                *(__half2*)(C + o1) = __floats2half2_rn(v2, v3);
            } else {
                float* C = (float*)Cv;
                if (RES) {
                    v0 += res[o0]; v1 += res[o0 + 1];
                    v2 += res[o1]; v3 += res[o1 + 1];
                }
                *(float2*)(C + o0) = make_float2(v0, v1);
                *(float2*)(C + o1) = make_float2(v2, v3);
            }
        }
    }
}

// ---------------- attention: one warp per (b, h); 2-key softmax -----------
__global__ void attn_kernel(const __half* __restrict__ q,
                            const __half* __restrict__ kv2,
                            const __half* __restrict__ kv3,
                            __half* __restrict__ attn,
                            float* __restrict__ wout) {
    int gw   = (blockIdx.x * blockDim.x + threadIdx.x) >> 5;   // b*16 + h
    int lane = threadIdx.x & 31;
    int b = gw >> 4;
    int h = gw & 15;
    size_t qoff = (size_t)b*FEAT_     + h*HDIM + lane*4;
    size_t koff = (size_t)b*(2*FEAT_) + h*HDIM + lane*4;

    uint2 qr = *(const uint2*)(q   + qoff);
    uint2 k2r = *(const uint2*)(kv2 + koff);
    uint2 k3r = *(const uint2*)(kv3 + koff);
    uint2 v2r = *(const uint2*)(kv2 + koff + FEAT_);
    uint2 v3r = *(const uint2*)(kv3 + koff + FEAT_);

    float2 qa = __half22float2(*(__half2*)&qr.x);
    float2 qb = __half22float2(*(__half2*)&qr.y);
    float2 k2a = __half22float2(*(__half2*)&k2r.x);
    float2 k2b = __half22float2(*(__half2*)&k2r.y);
    float2 k3a = __half22float2(*(__half2*)&k3r.x);
    float2 k3b = __half22float2(*(__half2*)&k3r.y);
    float2 v2a = __half22float2(*(__half2*)&v2r.x);
    float2 v2b = __half22float2(*(__half2*)&v2r.y);
    float2 v3a = __half22float2(*(__half2*)&v3r.x);
    float2 v3b = __half22float2(*(__half2*)&v3r.y);

    float s2 = qa.x*k2a.x + qa.y*k2a.y + qb.x*k2b.x + qb.y*k2b.y;
    float s3 = qa.x*k3a.x + qa.y*k3a.y + qb.x*k3b.x + qb.y*k3b.y;
    #pragma unroll
    for (int o = 16; o; o >>= 1) {
        s2 += __shfl_xor_sync(0xffffffffu, s2, o);
        s3 += __shfl_xor_sync(0xffffffffu, s3, o);
    }
    const float scale = 0.08838834764831845f;   // 1/sqrt(128)
    s2 *= scale; s3 *= scale;
    float m  = fmaxf(s2, s3);
    float e2 = expf(s2 - m), e3 = expf(s3 - m);
    float inv = 1.f / (e2 + e3);
    float w2 = e2 * inv, w3 = e3 * inv;

    __half2 p0 = __floats2half2_rn(w2*v2a.x + w3*v3a.x, w2*v2a.y + w3*v3a.y);
    __half2 p1 = __floats2half2_rn(w2*v2b.x + w3*v3b.x, w2*v2b.y + w3*v3b.y);
    uint2 ov;
    ov.x = *(uint32_t*)&p0;
    ov.y = *(uint32_t*)&p1;
    *(uint2*)(attn + qoff) = ov;

    if (lane == 0) {
        wout[(size_t)gw*2]     = w2;
        wout[(size_t)gw*2 + 1] = w3;
    }
}

// ---------------- LayerNorm: one block per row ----------------------------
__global__ void ln_kernel(const float* __restrict__ y,
                          const float* __restrict__ lw,
                          const float* __restrict__ lb,
                          float* __restrict__ out) {
    __shared__ float shs[8], shq[8];
    int row = blockIdx.x, t = threadIdx.x;
    const float4* yr = (const float4*)(y + (size_t)row*CURD);
    float4 a = yr[t];
    float4 b = yr[256 + t];
    float s  = a.x+a.y+a.z+a.w + b.x+b.y+b.z+b.w;
    float qq = a.x*a.x+a.y*a.y+a.z*a.z+a.w*a.w
             + b.x*b.x+b.y*b.y+b.z*b.z+b.w*b.w;
    #pragma unroll
    for (int o = 16; o; o >>= 1) {
        s  += __shfl_xor_sync(0xffffffffu, s,  o);
        qq += __shfl_xor_sync(0xffffffffu, qq, o);
    }
    int warp = t >> 5;
    if ((t & 31) == 0) { shs[warp] = s; shq[warp] = qq; }
    __syncthreads();
    float S = 0.f, Q = 0.f;
    #pragma unroll
    for (int i = 0; i < 8; i++) { S += shs[i]; Q += shq[i]; }
    float mean = S * (1.f/2048.f);
    float inv  = rsqrtf(Q * (1.f/2048.f) - mean*mean + 1e-5f);

    const float4* lw4 = (const float4*)lw;
    const float4* lb4 = (const float4*)lb;
    float4* orow = (float4*)(out + (size_t)row*CURD);
    float4 w, z, o4;
    w = lw4[t];       z = lb4[t];
    o4.x = w.x*(a.x-mean)*inv + z.x;
    o4.y = w.y*(a.y-mean)*inv + z.y;
    o4.z = w.z*(a.z-mean)*inv + z.z;
    o4.w = w.w*(a.w-mean)*inv + z.w;
    orow[t] = o4;
    w = lw4[256+t];   z = lb4[256+t];
    o4.x = w.x*(b.x-mean)*inv + z.x;
    o4.y = w.y*(b.y-mean)*inv + z.y;
    o4.z = w.z*(b.z-mean)*inv + z.z;
    o4.w = w.w*(b.w-mean)*inv + z.w;
    orow[256+t] = o4;
}

// ---------------- launch ---------------------------------------------------
extern "C" void kernel_launch(void* const* d_in, const int* in_sizes, int n_in,
                              void* d_out, int out_size) {
    const float* x   = (const float*)d_in[0];
    const float* v2  = (const float*)d_in[1];
    const float* v3  = (const float*)d_in[2];
    const float* Wq  = (const float*)d_in[3];
    const float* bq  = (const float*)d_in[4];
    const float* Wk2 = (const float*)d_in[5];
    const float* bk2 = (const float*)d_in[6];
    const float* Wk3 = (const float*)d_in[7];
    const float* bk3 = (const float*)d_in[8];
    const float* Wv2 = (const float*)d_in[9];
    const float* bv2 = (const float*)d_in[10];
    const float* Wv3 = (const float*)d_in[11];
    const float* bv3 = (const float*)d_in[12];
    const float* Wo  = (const float*)d_in[13];
    const float* bo  = (const float*)d_in[14];
    const float* lw  = (const float*)d_in[15];
    const float* lb  = (const float*)d_in[16];
    float* out = (float*)d_out;

    __half *xh, *v2h, *v3h, *wqh, *wk2h, *wv2h, *wk3h, *wv3h, *woh;
    __half *qb, *kv2, *kv3, *attn;
    float *yb;
    cudaGetSymbolAddress((void**)&xh,   g_xh);
    cudaGetSymbolAddress((void**)&v2h,  g_v2h);
    cudaGetSymbolAddress((void**)&v3h,  g_v3h);
    cudaGetSymbolAddress((void**)&wqh,  g_wqh);
    cudaGetSymbolAddress((void**)&wk2h, g_wk2h);
    cudaGetSymbolAddress((void**)&wv2h, g_wv2h);
    cudaGetSymbolAddress((void**)&wk3h, g_wk3h);
    cudaGetSymbolAddress((void**)&wv3h, g_wv3h);
    cudaGetSymbolAddress((void**)&woh,  g_woh);
    cudaGetSymbolAddress((void**)&qb,   g_q);
    cudaGetSymbolAddress((void**)&kv2,  g_kv2);
    cudaGetSymbolAddress((void**)&kv3,  g_kv3);
    cudaGetSymbolAddress((void**)&attn, g_att);
    cudaGetSymbolAddress((void**)&yb,   g_y);

    cudaFuncSetAttribute((const void*)gemm_f16_kernel<false,true>,
                         cudaFuncAttributeMaxDynamicSharedMemorySize, SMEM_BYTES);
    cudaFuncSetAttribute((const void*)gemm_f16_kernel<true,false>,
                         cudaFuncAttributeMaxDynamicSharedMemorySize, SMEM_BYTES);

    const int RG = 2048, RT = 256;
    conv_h_kernel<<<RG, RT>>>(x,   xh,  (long long)B_*CURD/4);
    conv_h_kernel<<<RG, RT>>>(v2,  v2h, (long long)B_*FEAT_/4);
    conv_h_kernel<<<RG, RT>>>(v3,  v3h, (long long)B_*FEAT_/4);
    conv_h_kernel<<<RG, RT>>>(Wq,  wqh, (long long)FEAT_*CURD/4);
    conv_h_kernel<<<RG, RT>>>(Wk2, wk2h,(long long)FEAT_*FEAT_/4);
    conv_h_kernel<<<RG, RT>>>(Wv2, wv2h,(long long)FEAT_*FEAT_/4);
    conv_h_kernel<<<RG, RT>>>(Wk3, wk3h,(long long)FEAT_*FEAT_/4);
    conv_h_kernel<<<RG, RT>>>(Wv3, wv3h,(long long)FEAT_*FEAT_/4);
    conv_h_kernel<<<RG, RT>>>(Wo,  woh, (long long)CURD*FEAT_/4);

    dim3 blk(NTHREADS);
    // q = x @ Wq^T + bq          (fp16 out)
    gemm_f16_kernel<false,true><<<dim3(FEAT_/BN, B_/BM), blk, SMEM_BYTES>>>(
        xh, wqh, wqh, FEAT_, bq, bq, nullptr, qb, FEAT_, CURD);
    // [k2 | v2] = v2 @ [Wk2; Wv2]^T + [bk2; bv2]   (fp16 out)
    gemm_f16_kernel<false,true><<<dim3(2*FEAT_/BN, B_/BM), blk, SMEM_BYTES>>>(
        v2h, wk2h, wv2h, FEAT_, bk2, bv2, nullptr, kv2, 2*FEAT_, FEAT_);
    // [k3 | v3] = v3 @ [Wk3; Wv3]^T + [bk3; bv3]   (fp16 out)
    gemm_f16_kernel<false,true><<<dim3(2*FEAT_/BN, B_/BM), blk, SMEM_BYTES>>>(
        v3h, wk3h, wv3h, FEAT_, bk3, bv3, nullptr, kv3, 2*FEAT_, FEAT_);

    // attention + attn_weights (written to the tail of d_out)
    size_t woff = (size_t)out_size - (size_t)B_*HEADS_*2;
    attn_kernel<<<B_*HEADS_/8, 256>>>(qb, kv2, kv3, attn, out + woff);

    // y = x + attn @ Wo^T + bo   (residual fused, exact fp32 x; fp32 out)
    gemm_f16_kernel<true,false><<<dim3(CURD/BN, B_/BM), blk, SMEM_BYTES>>>(
        attn, woh, woh, CURD, bo, bo, x, yb, CURD, FEAT_);

    // LayerNorm -> d_out
    ln_kernel<<<B_, 256>>>(yb, lw, lb, out);
}

// round 9
// speedup vs baseline: 1.9022x; 1.2442x over previous
#include <cuda_runtime.h>
#include <cuda_fp16.h>
#include <cstdint>

#define B_    16384
#define CURD  2048
#define FEAT_ 2048
#define HEADS_ 16
#define HDIM  128

#define NTHREADS 256
#define BM 128
#define BN 128
#define BK 64
// stage: 128 rows x 128 bytes (64 halves) per matrix
#define STAGE_B   16384
#define SMEM_BYTES (4*STAGE_B)        // A x2 stages + B x2 stages = 64 KB

// ---------------- scratch (device globals; no allocation allowed) ----------
__device__ __align__(16) __half g_xh [(size_t)B_*CURD];
__device__ __align__(16) __half g_v2h[(size_t)B_*FEAT_];
__device__ __align__(16) __half g_v3h[(size_t)B_*FEAT_];
__device__ __align__(16) __half g_wqh [(size_t)FEAT_*CURD];
__device__ __align__(16) __half g_wk2h[(size_t)FEAT_*FEAT_];
__device__ __align__(16) __half g_wv2h[(size_t)FEAT_*FEAT_];
__device__ __align__(16) __half g_wk3h[(size_t)FEAT_*FEAT_];
__device__ __align__(16) __half g_wv3h[(size_t)FEAT_*FEAT_];
__device__ __align__(16) __half g_woh [(size_t)CURD*FEAT_];
__device__ __align__(16) __half g_q  [(size_t)B_*FEAT_];
__device__ __align__(16) __half g_kv2[(size_t)B_*2*FEAT_];
__device__ __align__(16) __half g_kv3[(size_t)B_*2*FEAT_];
__device__ __align__(16) __half g_att[(size_t)B_*FEAT_];
__device__ __align__(16) float  g_y  [(size_t)B_*CURD];

// ---------------- helpers ----------------
__device__ __forceinline__ void cpa16(uint32_t s, const void* g) {
    asm volatile("cp.async.cg.shared.global [%0], [%1], 16;\n" :: "r"(s), "l"(g));
}

__device__ __forceinline__ void ldsm4(uint32_t* r, uint32_t addr) {
    asm volatile("ldmatrix.sync.aligned.m8n8.x4.shared.b16 {%0,%1,%2,%3}, [%4];"
        : "=r"(r[0]), "=r"(r[1]), "=r"(r[2]), "=r"(r[3]) : "r"(addr));
}

__device__ __forceinline__ void mma_f16(float* c, const uint32_t* a, const uint32_t* b) {
    asm volatile(
        "mma.sync.aligned.m16n8k16.row.col.f32.f16.f16.f32 "
        "{%0,%1,%2,%3}, {%4,%5,%6,%7}, {%8,%9}, {%0,%1,%2,%3};"
        : "+f"(c[0]), "+f"(c[1]), "+f"(c[2]), "+f"(c[3])
        : "r"(a[0]), "r"(a[1]), "r"(a[2]), "r"(a[3]),
          "r"(b[0]), "r"(b[1]));
}

// ---------------- fp32 -> fp16 conversion (RN) ------------------------------
__global__ void conv_h_kernel(const float* __restrict__ in,
                              __half* __restrict__ out, long long n4) {
    long long i  = blockIdx.x * (long long)blockDim.x + threadIdx.x;
    long long st = (long long)gridDim.x * blockDim.x;
    const float4* in4 = (const float4*)in;
    __half2* o2 = (__half2*)out;
    for (; i < n4; i += st) {
        float4 v = in4[i];
        o2[2*i]   = __floats2half2_rn(v.x, v.y);
        o2[2*i+1] = __floats2half2_rn(v.z, v.w);
    }
}

// ---------------- FP16 GEMM:  C[M,N] = A[M,K] @ W[N,K]^T + bias (+res)
// SW128-swizzled smem, ldmatrix fragment loads, warp grid 2(M) x 4(N),
// warp tile 64x32, BK=64 double-buffered cp.async.
// W split into two stacked halves (W0 rows [0,Nsplit), W1 the rest).
template<bool RES, bool HOUT>
__global__ __launch_bounds__(NTHREADS, 2)
void gemm_f16_kernel(const __half* __restrict__ A,
                     const __half* __restrict__ W0,
                     const __half* __restrict__ W1,
                     int Nsplit,
                     const float* __restrict__ bias0,
                     const float* __restrict__ bias1,
                     const float* __restrict__ res,
                     void* __restrict__ Cv,
                     int N, int K) {
    extern __shared__ __align__(1024) char smem[];
    const uint32_t sbase = (uint32_t)__cvta_generic_to_shared(smem);
    const uint32_t sA = sbase;              // 2 stages of A: [0, 2*STAGE_B)
    const uint32_t sB = sbase + 2*STAGE_B;  // 2 stages of B

    const int nb = blockIdx.x, mb = blockIdx.y;
    const __half* Wp; const float* biasP; int nloc0;
    if (nb*BN < Nsplit) { Wp = W0; biasP = bias0; nloc0 = nb*BN; }
    else                { Wp = W1; biasP = bias1; nloc0 = nb*BN - Nsplit; }

    const int tid  = threadIdx.x;
    const int warp = tid >> 5, lane = tid & 31;
    const int wm = warp & 1;           // 2 M-rows of warps (64 rows each)
    const int wn = warp >> 1;          // 4 N-cols of warps (32 cols each)
    const int qr = lane >> 2, qc = lane & 3;

    // ---- staging addressing (per thread: one row-half = 64B = 4x16B) ----
    const int srow = tid >> 1;                  // 0..127
    const int scol = (tid & 1) * 64;            // byte col 0 or 64
    const uint32_t sxor = (uint32_t)((srow & 7) << 4);
    const uint32_t sdst = srow*128 + (((uint32_t)scol) ^ sxor);  // +i*16 (XOR-safe: bits 4-6 const per i? no: i*16 toggles bit4-6)
    // note: (scol + i*16) ^ sxor must be computed per chunk; sxor only flips bits 4..6
    const __half* Ag = A  + (size_t)(mb*BM + srow)*K + scol/2;
    const __half* Bg = Wp + (size_t)(nloc0 + srow)*K + scol/2;

    // ---- ldmatrix addressing ----
    const int j  = lane >> 3;          // matrix index 0..3
    const int rr = lane & 7;
    const uint32_t fxor = (uint32_t)(rr << 4);
    // A: x4 covers one m16k16 tile: matrices [m0-7,k0-7],[m8-15,k0-7],[m0-7,k8-15],[m8-15,k8-15]
    const uint32_t aRow  = (uint32_t)(wm*64 + (j&1)*8 + rr);
    const uint32_t aKoff = (uint32_t)((j>>1)*16);
    // B: x4 covers two n8k16 tiles: [n0-7,k0-7],[n0-7,k8-15],[n8-15,k0-7],[n8-15,k8-15]
    const uint32_t bRow  = (uint32_t)(wn*32 + (j>>1)*8 + rr);
    const uint32_t bKoff = (uint32_t)((j&1)*16);

    float acc[4][4][4];
    #pragma unroll
    for (int i = 0; i < 4; i++)
        #pragma unroll
        for (int jn = 0; jn < 4; jn++)
            #pragma unroll
            for (int l = 0; l < 4; l++) acc[i][jn][l] = 0.f;

    const int KT = K / BK;

    // ---- prologue: stage 0 ----
    {
        #pragma unroll
        for (int i = 0; i < 4; i++) {
            uint32_t c = ((uint32_t)(scol + i*16)) ^ sxor;
            cpa16(sA + srow*128 + c, Ag + i*8);
            cpa16(sB + srow*128 + c, Bg + i*8);
        }
        asm volatile("cp.async.commit_group;\n" ::);
        asm volatile("cp.async.wait_group 0;\n" ::);
        __syncthreads();
    }

    int buf = 0;
    for (int kt = 0; kt < KT; kt++) {
        if (kt + 1 < KT) {
            const int nbuf = buf ^ 1;
            const __half* Agk = Ag + (kt+1)*BK;
            const __half* Bgk = Bg + (kt+1)*BK;
            #pragma unroll
            for (int i = 0; i < 4; i++) {
                uint32_t c = ((uint32_t)(scol + i*16)) ^ sxor;
                cpa16(sA + nbuf*STAGE_B + srow*128 + c, Agk + i*8);
                cpa16(sB + nbuf*STAGE_B + srow*128 + c, Bgk + i*8);
            }
            asm volatile("cp.async.commit_group;\n" ::);
        }

        const uint32_t aBase = sA + buf*STAGE_B + aRow*128;
        const uint32_t bBase = sB + buf*STAGE_B + bRow*128;
        #pragma unroll
        for (int ks = 0; ks < BK/16; ks++) {
            uint32_t afr[4][4];
            const uint32_t ac = ((uint32_t)(ks*32) + aKoff) ^ fxor;
            #pragma unroll
            for (int mt = 0; mt < 4; mt++)
                ldsm4(afr[mt], aBase + mt*16*128 + ac);
            uint32_t bfr[8];
            const uint32_t bc = ((uint32_t)(ks*32) + bKoff) ^ fxor;
            ldsm4(bfr,     bBase + bc);             // n-subtiles 0,1
            ldsm4(bfr + 4, bBase + 16*128 + bc);    // n-subtiles 2,3
            #pragma unroll
            for (int mt = 0; mt < 4; mt++)
                #pragma unroll
                for (int nt = 0; nt < 4; nt++)
                    mma_f16(acc[mt][nt], afr[mt], bfr + nt*2);
        }

        asm volatile("cp.async.wait_group 0;\n" ::);
        __syncthreads();
        buf ^= 1;
    }

    // ---- epilogue: bias (+residual), fp16 or fp32 stores ----
    float bv0[4], bv1[4];
    #pragma unroll
    for (int nt = 0; nt < 4; nt++) {
        int cl = nloc0 + wn*32 + nt*8 + qc*2;
        bv0[nt] = biasP[cl];
        bv1[nt] = biasP[cl + 1];
    }
    #pragma unroll
    for (int mt = 0; mt < 4; mt++) {
        int r0 = mb*BM + wm*64 + mt*16 + qr;
        #pragma unroll
        for (int nt = 0; nt < 4; nt++) {
            int c0 = nb*BN + wn*32 + nt*8 + qc*2;
            size_t o0 = (size_t)r0*N + c0;
            size_t o1 = o0 + (size_t)8*N;
            float v0 = acc[mt][nt][0] + bv0[nt];
            float v1 = acc[mt][nt][1] + bv1[nt];
            float v2 = acc[mt][nt][2] + bv0[nt];
            float v3 = acc[mt][nt][3] + bv1[nt];
            if (HOUT) {
                __half* C = (__half*)Cv;
                *(__half2*)(C + o0) = __floats2half2_rn(v0, v1);
                *(__half2*)(C + o1) = __floats2half2_rn(v2, v3);
            } else {
                float* C = (float*)Cv;
                if (RES) {
                    v0 += res[o0]; v1 += res[o0 + 1];
                    v2 += res[o1]; v3 += res[o1 + 1];
                }
                *(float2*)(C + o0) = make_float2(v0, v1);
                *(float2*)(C + o1) = make_float2(v2, v3);
            }
        }
    }
}

// ---------------- attention: one warp per (b, h); 2-key softmax -----------
__global__ void attn_kernel(const __half* __restrict__ q,
                            const __half* __restrict__ kv2,
                            const __half* __restrict__ kv3,
                            __half* __restrict__ attn,
                            float* __restrict__ wout) {
    int gw   = (blockIdx.x * blockDim.x + threadIdx.x) >> 5;   // b*16 + h
    int lane = threadIdx.x & 31;
    int b = gw >> 4;
    int h = gw & 15;
    size_t qoff = (size_t)b*FEAT_     + h*HDIM + lane*4;
    size_t koff = (size_t)b*(2*FEAT_) + h*HDIM + lane*4;

    uint2 qr = *(const uint2*)(q   + qoff);
    uint2 k2r = *(const uint2*)(kv2 + koff);
    uint2 k3r = *(const uint2*)(kv3 + koff);
    uint2 v2r = *(const uint2*)(kv2 + koff + FEAT_);
    uint2 v3r = *(const uint2*)(kv3 + koff + FEAT_);

    float2 qa = __half22float2(*(__half2*)&qr.x);
    float2 qb = __half22float2(*(__half2*)&qr.y);
    float2 k2a = __half22float2(*(__half2*)&k2r.x);
    float2 k2b = __half22float2(*(__half2*)&k2r.y);
    float2 k3a = __half22float2(*(__half2*)&k3r.x);
    float2 k3b = __half22float2(*(__half2*)&k3r.y);
    float2 v2a = __half22float2(*(__half2*)&v2r.x);
    float2 v2b = __half22float2(*(__half2*)&v2r.y);
    float2 v3a = __half22float2(*(__half2*)&v3r.x);
    float2 v3b = __half22float2(*(__half2*)&v3r.y);

    float s2 = qa.x*k2a.x + qa.y*k2a.y + qb.x*k2b.x + qb.y*k2b.y;
    float s3 = qa.x*k3a.x + qa.y*k3a.y + qb.x*k3b.x + qb.y*k3b.y;
    #pragma unroll
    for (int o = 16; o; o >>= 1) {
        s2 += __shfl_xor_sync(0xffffffffu, s2, o);
        s3 += __shfl_xor_sync(0xffffffffu, s3, o);
    }
    const float scale = 0.08838834764831845f;   // 1/sqrt(128)
    s2 *= scale; s3 *= scale;
    float m  = fmaxf(s2, s3);
    float e2 = expf(s2 - m), e3 = expf(s3 - m);
    float inv = 1.f / (e2 + e3);
    float w2 = e2 * inv, w3 = e3 * inv;

    __half2 p0 = __floats2half2_rn(w2*v2a.x + w3*v3a.x, w2*v2a.y + w3*v3a.y);
    __half2 p1 = __floats2half2_rn(w2*v2b.x + w3*v3b.x, w2*v2b.y + w3*v3b.y);
    uint2 ov;
    ov.x = *(uint32_t*)&p0;
    ov.y = *(uint32_t*)&p1;
    *(uint2*)(attn + qoff) = ov;

    if (lane == 0) {
        wout[(size_t)gw*2]     = w2;
        wout[(size_t)gw*2 + 1] = w3;
    }
}

// ---------------- LayerNorm: one block per row ----------------------------
__global__ void ln_kernel(const float* __restrict__ y,
                          const float* __restrict__ lw,
                          const float* __restrict__ lb,
                          float* __restrict__ out) {
    __shared__ float shs[8], shq[8];
    int row = blockIdx.x, t = threadIdx.x;
    const float4* yr = (const float4*)(y + (size_t)row*CURD);
    float4 a = yr[t];
    float4 b = yr[256 + t];
    float s  = a.x+a.y+a.z+a.w + b.x+b.y+b.z+b.w;
    float qq = a.x*a.x+a.y*a.y+a.z*a.z+a.w*a.w
             + b.x*b.x+b.y*b.y+b.z*b.z+b.w*b.w;
    #pragma unroll
    for (int o = 16; o; o >>= 1) {
        s  += __shfl_xor_sync(0xffffffffu, s,  o);
        qq += __shfl_xor_sync(0xffffffffu, qq, o);
    }
    int warp = t >> 5;
    if ((t & 31) == 0) { shs[warp] = s; shq[warp] = qq; }
    __syncthreads();
    float S = 0.f, Q = 0.f;
    #pragma unroll
    for (int i = 0; i < 8; i++) { S += shs[i]; Q += shq[i]; }
    float mean = S * (1.f/2048.f);
    float inv  = rsqrtf(Q * (1.f/2048.f) - mean*mean + 1e-5f);

    const float4* lw4 = (const float4*)lw;
    const float4* lb4 = (const float4*)lb;
    float4* orow = (float4*)(out + (size_t)row*CURD);
    float4 w, z, o4;
    w = lw4[t];       z = lb4[t];
    o4.x = w.x*(a.x-mean)*inv + z.x;
    o4.y = w.y*(a.y-mean)*inv + z.y;
    o4.z = w.z*(a.z-mean)*inv + z.z;
    o4.w = w.w*(a.w-mean)*inv + z.w;
    orow[t] = o4;
    w = lw4[256+t];   z = lb4[256+t];
    o4.x = w.x*(b.x-mean)*inv + z.x;
    o4.y = w.y*(b.y-mean)*inv + z.y;
    o4.z = w.z*(b.z-mean)*inv + z.z;
    o4.w = w.w*(b.w-mean)*inv + z.w;
    orow[256+t] = o4;
}

// ---------------- launch ---------------------------------------------------
extern "C" void kernel_launch(void* const* d_in, const int* in_sizes, int n_in,
                              void* d_out, int out_size) {
    const float* x   = (const float*)d_in[0];
    const float* v2  = (const float*)d_in[1];
    const float* v3  = (const float*)d_in[2];
    const float* Wq  = (const float*)d_in[3];
    const float* bq  = (const float*)d_in[4];
    const float* Wk2 = (const float*)d_in[5];
    const float* bk2 = (const float*)d_in[6];
    const float* Wk3 = (const float*)d_in[7];
    const float* bk3 = (const float*)d_in[8];
    const float* Wv2 = (const float*)d_in[9];
    const float* bv2 = (const float*)d_in[10];
    const float* Wv3 = (const float*)d_in[11];
    const float* bv3 = (const float*)d_in[12];
    const float* Wo  = (const float*)d_in[13];
    const float* bo  = (const float*)d_in[14];
    const float* lw  = (const float*)d_in[15];
    const float* lb  = (const float*)d_in[16];
    float* out = (float*)d_out;

    __half *xh, *v2h, *v3h, *wqh, *wk2h, *wv2h, *wk3h, *wv3h, *woh;
    __half *qb, *kv2, *kv3, *attn;
    float *yb;
    cudaGetSymbolAddress((void**)&xh,   g_xh);
    cudaGetSymbolAddress((void**)&v2h,  g_v2h);
    cudaGetSymbolAddress((void**)&v3h,  g_v3h);
    cudaGetSymbolAddress((void**)&wqh,  g_wqh);
    cudaGetSymbolAddress((void**)&wk2h, g_wk2h);
    cudaGetSymbolAddress((void**)&wv2h, g_wv2h);
    cudaGetSymbolAddress((void**)&wk3h, g_wk3h);
    cudaGetSymbolAddress((void**)&wv3h, g_wv3h);
    cudaGetSymbolAddress((void**)&woh,  g_woh);
    cudaGetSymbolAddress((void**)&qb,   g_q);
    cudaGetSymbolAddress((void**)&kv2,  g_kv2);
    cudaGetSymbolAddress((void**)&kv3,  g_kv3);
    cudaGetSymbolAddress((void**)&attn, g_att);
    cudaGetSymbolAddress((void**)&yb,   g_y);

    cudaFuncSetAttribute((const void*)gemm_f16_kernel<false,true>,
                         cudaFuncAttributeMaxDynamicSharedMemorySize, SMEM_BYTES);
    cudaFuncSetAttribute((const void*)gemm_f16_kernel<true,false>,
                         cudaFuncAttributeMaxDynamicSharedMemorySize, SMEM_BYTES);

    const int RG = 2048, RT = 256;
    conv_h_kernel<<<RG, RT>>>(x,   xh,  (long long)B_*CURD/4);
    conv_h_kernel<<<RG, RT>>>(v2,  v2h, (long long)B_*FEAT_/4);
    conv_h_kernel<<<RG, RT>>>(v3,  v3h, (long long)B_*FEAT_/4);
    conv_h_kernel<<<RG, RT>>>(Wq,  wqh, (long long)FEAT_*CURD/4);
    conv_h_kernel<<<RG, RT>>>(Wk2, wk2h,(long long)FEAT_*FEAT_/4);
    conv_h_kernel<<<RG, RT>>>(Wv2, wv2h,(long long)FEAT_*FEAT_/4);
    conv_h_kernel<<<RG, RT>>>(Wk3, wk3h,(long long)FEAT_*FEAT_/4);
    conv_h_kernel<<<RG, RT>>>(Wv3, wv3h,(long long)FEAT_*FEAT_/4);
    conv_h_kernel<<<RG, RT>>>(Wo,  woh, (long long)CURD*FEAT_/4);

    dim3 blk(NTHREADS);
    // q = x @ Wq^T + bq          (fp16 out)
    gemm_f16_kernel<false,true><<<dim3(FEAT_/BN, B_/BM), blk, SMEM_BYTES>>>(
        xh, wqh, wqh, FEAT_, bq, bq, nullptr, qb, FEAT_, CURD);
    // [k2 | v2] = v2 @ [Wk2; Wv2]^T + [bk2; bv2]   (fp16 out)
    gemm_f16_kernel<false,true><<<dim3(2*FEAT_/BN, B_/BM), blk, SMEM_BYTES>>>(
        v2h, wk2h, wv2h, FEAT_, bk2, bv2, nullptr, kv2, 2*FEAT_, FEAT_);
    // [k3 | v3] = v3 @ [Wk3; Wv3]^T + [bk3; bv3]   (fp16 out)
    gemm_f16_kernel<false,true><<<dim3(2*FEAT_/BN, B_/BM), blk, SMEM_BYTES>>>(
        v3h, wk3h, wv3h, FEAT_, bk3, bv3, nullptr, kv3, 2*FEAT_, FEAT_);

    // attention + attn_weights (written to the tail of d_out)
    size_t woff = (size_t)out_size - (size_t)B_*HEADS_*2;
    attn_kernel<<<B_*HEADS_/8, 256>>>(qb, kv2, kv3, attn, out + woff);

    // y = x + attn @ Wo^T + bo   (residual fused, exact fp32 x; fp32 out)
    gemm_f16_kernel<true,false><<<dim3(CURD/BN, B_/BM), blk, SMEM_BYTES>>>(
        attn, woh, woh, CURD, bo, bo, x, yb, CURD, FEAT_);

    // LayerNorm -> d_out
    ln_kernel<<<B_, 256>>>(yb, lw, lb, out);
}